// round 14
// baseline (speedup 1.0000x reference)
#include <cuda_runtime.h>
#include <cstdint>
#include <math.h>

// Problem constants
#define BB 4
#define LL 2048
#define EE 1024
#define HH 16
#define DD 64
#define ML (BB * LL)   // 8192 total rows

// Scratch (device globals: allocation-free per harness rules)
__device__ float g_q[ML * EE];
__device__ float g_k[ML * EE];
__device__ float g_v[ML * EE];
__device__ float g_ctx[ML * EE];
__device__ float g_rq[ML * EE];
__device__ float g_rk[ML * EE];
__device__ float g_rv[ML * EE];
__device__ float g_rw[4 * EE * EE];
__device__ uint32_t g_mb[ML * (LL / 32)];   // mask bitmap: 2 MB

// ---------------------------------------------------------------------------
// Helpers
// ---------------------------------------------------------------------------
__device__ __forceinline__ uint32_t smem_u32(const void* p) {
    uint32_t a;
    asm("{ .reg .u64 t; cvta.to.shared.u64 t, %1; cvt.u32.u64 %0, t; }"
        : "=r"(a) : "l"(p));
    return a;
}

#define CP_ASYNC16(smem_addr, gptr) \
    asm volatile("cp.async.cg.shared.global [%0], [%1], 16;" \
                 :: "r"(smem_addr), "l"(gptr) : "memory")

__device__ __forceinline__ float rna(float f) {
    uint32_t r;
    asm("cvt.rna.tf32.f32 %0, %1;" : "=r"(r) : "f"(f));
    return __uint_as_float(r);
}

__device__ __forceinline__ void mma_tf32(float* c, const uint32_t* a,
                                         const uint32_t* b) {
    asm volatile(
        "mma.sync.aligned.m16n8k8.row.col.f32.tf32.tf32.f32 "
        "{%0,%1,%2,%3}, {%4,%5,%6,%7}, {%8,%9}, {%0,%1,%2,%3};"
        : "+f"(c[0]), "+f"(c[1]), "+f"(c[2]), "+f"(c[3])
        : "r"(a[0]), "r"(a[1]), "r"(a[2]), "r"(a[3]), "r"(b[0]), "r"(b[1]));
}

// ldmatrix x4: 4 m8n8.b16 tiles; for tf32 each tile = 8 rows x 4 floats.
// Result: reg t, lane i  <-  tile t, row i/4, float i%4  (= the tf32 frag map)
#define LDSM_X4(r0, r1, r2, r3, addr) \
    asm volatile("ldmatrix.sync.aligned.m8n8.x4.shared.b16 {%0,%1,%2,%3}, [%4];" \
                 : "=r"(r0), "=r"(r1), "=r"(r2), "=r"(r3) : "r"(addr))

// ---------------------------------------------------------------------------
// Batched pre-rounding: one launch rounds all 7 arrays (blockIdx.y selects).
// ---------------------------------------------------------------------------
struct RoundArgs {
    const float* src[7];
    float* dst[7];
    int n4[7];
};

__global__ void round_all(RoundArgs ra) {
    const int a = blockIdx.y;
    const float4* s = (const float4*)ra.src[a];
    float4* d = (float4*)ra.dst[a];
    const int n4 = ra.n4[a];
    int i = blockIdx.x * blockDim.x + threadIdx.x;
    const int stride = gridDim.x * blockDim.x;
    for (; i < n4; i += stride) {
        float4 v = s[i];
        v.x = rna(v.x); v.y = rna(v.y); v.z = rna(v.z); v.w = rna(v.w);
        d[i] = v;
    }
}

// ---------------------------------------------------------------------------
// Mask -> bitmap: bit set = keep (mask != 0). 67 MB -> 2 MB, read once.
// ---------------------------------------------------------------------------
__global__ void mask_to_bits(const int* __restrict__ mask) {
    const int row = blockIdx.x;                    // 0 .. ML-1  (= b*LL + q)
    const int* mrow = mask + (size_t)row * LL;
    const int lane = threadIdx.x & 31;
    const int warp = threadIdx.x >> 5;
#pragma unroll
    for (int w = warp; w < LL / 32; w += 8) {
        const int v = mrow[w * 32 + lane];
        const uint32_t bits = __ballot_sync(0xffffffffu, v != 0);
        if (lane == 0) g_mb[row * (LL / 32) + w] = bits;
    }
}

// ---------------------------------------------------------------------------
// mma.sync tf32 GEMM v3 (unchanged from R12 WIN): 3-stage pipeline, 1 barrier.
// ---------------------------------------------------------------------------
#define GBK 32
#define NKT32 (EE / GBK)
#define SSTR 36
#define TILE_F (128 * SSTR)
#define STAGE_F (2 * TILE_F)
#define GSTAGES 3
#define GEMM_SMEM (GSTAGES * STAGE_F * 4)   // 110592 B

template <int ROUND_OUT>
__device__ __forceinline__ void gemm_body(const float* __restrict__ A,
                                          const float* __restrict__ W,
                                          const float* __restrict__ bias,
                                          float* __restrict__ C,
                                          float* sm) {
    const int tid = threadIdx.x;
    const int lane = tid & 31;
    const int warp = tid >> 5;
    const int wm = (warp >> 2) * 64;
    const int wn = (warp & 3) * 32;
    const int bm = blockIdx.x * 128;
    const int bn = blockIdx.y * 128;
    const uint32_t sb = smem_u32(sm);

    const int lrow = tid >> 3;
    const int lc4 = (tid & 7) * 4;
    const int lg = lane >> 2;
    const int lk = lane & 3;

    float c[4][4][4];
#pragma unroll
    for (int mt = 0; mt < 4; mt++)
#pragma unroll
        for (int nt = 0; nt < 4; nt++)
#pragma unroll
            for (int i = 0; i < 4; i++) c[mt][nt][i] = 0.0f;

    const float* gA0 = A + (size_t)(bm + lrow) * EE + lc4;
    const float* gW0 = W + (size_t)(bn + lrow) * EE + lc4;
    const uint32_t sOff = (lrow * SSTR + lc4) * 4;

#define LOAD_STAGE(kt, s) do {                                                 \
        const float* _ga = gA0 + (size_t)(kt) * GBK;                           \
        const float* _gw = gW0 + (size_t)(kt) * GBK;                           \
        uint32_t _sa = sb + (uint32_t)((s) * STAGE_F * 4) + sOff;              \
        uint32_t _sw = _sa + TILE_F * 4;                                       \
        _Pragma("unroll")                                                      \
        for (int _u = 0; _u < 4; _u++) {                                       \
            CP_ASYNC16(_sa + _u * 32 * SSTR * 4, _ga + (size_t)_u * 32 * EE);  \
            CP_ASYNC16(_sw + _u * 32 * SSTR * 4, _gw + (size_t)_u * 32 * EE);  \
        }                                                                      \
        asm volatile("cp.async.commit_group;" ::: "memory");                   \
    } while (0)

    LOAD_STAGE(0, 0);
    LOAD_STAGE(1, 1);

    for (int kt = 0; kt < NKT32; kt++) {
        if (kt + 1 < NKT32) {
            asm volatile("cp.async.wait_group 1;" ::: "memory");
        } else {
            asm volatile("cp.async.wait_group 0;" ::: "memory");
        }
        __syncthreads();

        if (kt + 2 < NKT32) LOAD_STAGE(kt + 2, (kt + 2) % GSTAGES);

        const float* As = sm + (kt % GSTAGES) * STAGE_F;
        const float* Ws = As + TILE_F;

#pragma unroll
        for (int ks = 0; ks < 4; ks++) {
            const int k0 = ks * 8;
            uint32_t bfr[4][2];
            uint32_t afr[4][4];
#pragma unroll
            for (int nt = 0; nt < 4; nt++) {
                const int r = wn + nt * 8 + lg;
                bfr[nt][0] = __float_as_uint(Ws[r * SSTR + k0 + lk]);
                bfr[nt][1] = __float_as_uint(Ws[r * SSTR + k0 + 4 + lk]);
            }
#pragma unroll
            for (int mt = 0; mt < 4; mt++) {
                const int r = wm + mt * 16 + lg;
                afr[mt][0] = __float_as_uint(As[r * SSTR + k0 + lk]);
                afr[mt][1] = __float_as_uint(As[(r + 8) * SSTR + k0 + lk]);
                afr[mt][2] = __float_as_uint(As[r * SSTR + k0 + 4 + lk]);
                afr[mt][3] = __float_as_uint(As[(r + 8) * SSTR + k0 + 4 + lk]);
            }
#pragma unroll
            for (int mt = 0; mt < 4; mt++)
#pragma unroll
                for (int nt = 0; nt < 4; nt++)
                    mma_tf32(c[mt][nt], afr[mt], bfr[nt]);
        }
    }

#pragma unroll
    for (int mt = 0; mt < 4; mt++) {
        const int r0 = bm + wm + mt * 16 + lg;
#pragma unroll
        for (int nt = 0; nt < 4; nt++) {
            const int col = bn + wn + nt * 8 + lk * 2;
            float bx = 0.0f, by = 0.0f;
            if (bias) { bx = bias[col]; by = bias[col + 1]; }
            float2 v0, v1;
            v0.x = c[mt][nt][0] + bx;
            v0.y = c[mt][nt][1] + by;
            v1.x = c[mt][nt][2] + bx;
            v1.y = c[mt][nt][3] + by;
            if (ROUND_OUT) {
                v0.x = rna(v0.x); v0.y = rna(v0.y);
                v1.x = rna(v1.x); v1.y = rna(v1.y);
            }
            *(float2*)(C + (size_t)r0 * EE + col) = v0;
            *(float2*)(C + (size_t)(r0 + 8) * EE + col) = v1;
        }
    }
#undef LOAD_STAGE
}

struct QkvArgs {
    const float* A[3];
    const float* W;
    float* C[3];
};

__global__ __launch_bounds__(256, 2) void gemm_qkv(QkvArgs qa) {
    extern __shared__ float sm[];
    const int z = blockIdx.z;
    gemm_body<1>(qa.A[z], qa.W + (size_t)z * EE * EE, nullptr, qa.C[z], sm);
}

__global__ __launch_bounds__(256, 2) void gemm_out(const float* __restrict__ A,
                                                   const float* __restrict__ W,
                                                   const float* __restrict__ bias,
                                                   float* __restrict__ C) {
    extern __shared__ float sm[];
    gemm_body<0>(A, W, bias, C, sm);
}

// ---------------------------------------------------------------------------
// Tensor-core flash attention v4: v3 + ldmatrix fragment loads (Q/K/P) +
// mask all-ones fast path. Arithmetic bit-identical to v3.
// ---------------------------------------------------------------------------
#define AQ 68
#define AK 68
#define AV 72
#define AP 68
#define QF (256 * AQ)
#define STGF (64 * AK + 64 * AV)
#define PF (256 * AP)
#define ATTN_SMEM ((QF + 2 * STGF + PF) * 4)   // 210944 B

__global__ __launch_bounds__(256, 1) void attn_tc() {
    extern __shared__ float sm[];
    float* Qs = sm;
    float* St = Qs + QF;
    float* Ps = St + 2 * STGF;

    const int tid = threadIdx.x;
    const int lane = tid & 31;
    const int warp = tid >> 5;
    const int lg = lane >> 2;
    const int lk = lane & 3;
    const int wq = warp * 32;

    const int bh = blockIdx.y;
    const int b = bh >> 4;
    const int h = bh & 15;
    const int q0 = blockIdx.x * 256;

    const float scale = 0.03125f;
    const float mask_addend = -3.125e18f;

    const uint32_t sb = smem_u32(sm);
    const int ldr = tid >> 4;
    const int ldc = (tid & 15) << 2;

    // ldmatrix per-lane geometry: lanes 0-7 tile0 rows, 8-15 tile1, ...
    const int row8 = lane & 7;
    const int thalf = (lane >> 3) & 1;   // +8 rows for tiles 1,3
    const int tkoff = (lane >> 4) * 4;   // +4 floats (k+4) for tiles 2,3

    // Q / P ldmatrix base addresses (per mt). Per ks-step add ks*32 bytes.
    uint32_t qadr[2], padr[2];
#pragma unroll
    for (int mt = 0; mt < 2; mt++) {
        const int r = wq + mt * 16 + row8 + thalf * 8;
        qadr[mt] = sb + (uint32_t)(r * AQ + tkoff) * 4;
        padr[mt] = sb + (uint32_t)(QF + 2 * STGF + r * AP + tkoff) * 4;
    }
    // K ldmatrix lane offset (tiles = 4 consecutive k-quads of one nt row band)
    const uint32_t klane = (uint32_t)(row8 * AK + (lane >> 3) * 4) * 4;

#define PREFETCH_KV(kt, bufsel) do {                                            \
        const uint32_t so = sb + (uint32_t)(QF + (bufsel) * STGF) * 4;          \
        _Pragma("unroll")                                                       \
        for (int _u = 0; _u < 4; _u++) {                                        \
            const int _row = ldr + 16 * _u;                                     \
            const size_t _g = (size_t)(b * LL + (kt) * 64 + _row) * EE          \
                              + h * DD + ldc;                                   \
            CP_ASYNC16(so + (uint32_t)(_row * AK + ldc) * 4, g_k + _g);         \
            CP_ASYNC16(so + (uint32_t)(64 * AK + _row * AV + ldc) * 4,          \
                       g_v + _g);                                               \
        }                                                                       \
        asm volatile("cp.async.commit_group;" ::: "memory");                    \
    } while (0)

    PREFETCH_KV(0, 0);

#pragma unroll
    for (int u = 0; u < 16; u++) {
        int idx = tid + 256 * u;
        int row = idx >> 4;
        int c = (idx & 15) << 2;
        float4 q = *(const float4*)(g_q + (size_t)(b * LL + q0 + row) * EE + h * DD + c);
        q.x *= scale; q.y *= scale; q.z *= scale; q.w *= scale;
        *(float4*)(Qs + row * AQ + c) = q;
    }

    float o[2][8][4];
#pragma unroll
    for (int mt = 0; mt < 2; mt++)
#pragma unroll
        for (int dn = 0; dn < 8; dn++)
#pragma unroll
            for (int j = 0; j < 4; j++) o[mt][dn][j] = 0.0f;
    float mrow[2][2], lrow[2][2];
#pragma unroll
    for (int mt = 0; mt < 2; mt++) {
        mrow[mt][0] = -1e30f; mrow[mt][1] = -1e30f;
        lrow[mt][0] = 0.0f;   lrow[mt][1] = 0.0f;
    }

    for (int kt = 0; kt < LL / 64; kt++) {
        const int buf = kt & 1;

        // Prefetch mask words for this k-tile (L2-resident, tiny)
        uint2 mw0[2], mw1[2];
#pragma unroll
        for (int mt = 0; mt < 2; mt++) {
            const int qrow = q0 + wq + mt * 16 + lg;
            const int base = (b * LL + qrow) * (LL / 32) + kt * 2;
            mw0[mt] = *(const uint2*)(g_mb + base);
            mw1[mt] = *(const uint2*)(g_mb + base + 8 * (LL / 32));
        }

        asm volatile("cp.async.wait_group 0;" ::: "memory");
        __syncthreads();

        if (kt + 1 < LL / 64) PREFETCH_KV(kt + 1, buf ^ 1);

        const uint32_t sK = sb + (uint32_t)(QF + buf * STGF) * 4;
        const float* Vs = St + buf * STGF + 64 * AK;

        // ---- S = Q @ K^T (ldmatrix frags) ----
        float s[2][8][4];
#pragma unroll
        for (int mt = 0; mt < 2; mt++)
#pragma unroll
            for (int nt = 0; nt < 8; nt++)
#pragma unroll
                for (int j = 0; j < 4; j++) s[mt][nt][j] = 0.0f;

#pragma unroll
        for (int kb = 0; kb < 4; kb++) {            // 16-k blocks
            uint32_t kf[8][4];
#pragma unroll
            for (int nt = 0; nt < 8; nt++) {
                LDSM_X4(kf[nt][0], kf[nt][1], kf[nt][2], kf[nt][3],
                        sK + klane + (uint32_t)(nt * 8 * AK * 4 + kb * 64));
            }
#pragma unroll
            for (int half = 0; half < 2; half++) {  // 2 ks-steps per block
                const int ks = kb * 2 + half;
                uint32_t a0[4], a1[4];
                LDSM_X4(a0[0], a0[1], a0[2], a0[3], qadr[0] + ks * 32);
                LDSM_X4(a1[0], a1[1], a1[2], a1[3], qadr[1] + ks * 32);
#pragma unroll
                for (int nt = 0; nt < 8; nt++) {
                    uint32_t bf[2] = { kf[nt][half * 2], kf[nt][half * 2 + 1] };
                    mma_tf32(s[0][nt], a0, bf);
                    mma_tf32(s[1][nt], a1, bf);
                }
            }
        }

        // ---- mask from bitmap (skip when row segment is all-ones) ----
#pragma unroll
        for (int mt = 0; mt < 2; mt++) {
            const uint32_t and4 = mw0[mt].x & mw0[mt].y & mw1[mt].x & mw1[mt].y;
            if (and4 != 0xffffffffu) {
                const uint64_t m0 = (uint64_t)mw0[mt].x | ((uint64_t)mw0[mt].y << 32);
                const uint64_t m1 = (uint64_t)mw1[mt].x | ((uint64_t)mw1[mt].y << 32);
#pragma unroll
                for (int nt = 0; nt < 8; nt++) {
                    const int c = nt * 8 + 2 * lk;
                    if (!((m0 >> c) & 1))       s[mt][nt][0] = mask_addend;
                    if (!((m0 >> (c + 1)) & 1)) s[mt][nt][1] = mask_addend;
                    if (!((m1 >> c) & 1))       s[mt][nt][2] = mask_addend;
                    if (!((m1 >> (c + 1)) & 1)) s[mt][nt][3] = mask_addend;
                }
            }
        }

        // ---- online softmax + P store ----
#pragma unroll
        for (int mt = 0; mt < 2; mt++) {
            float mx0 = s[mt][0][0], mx1 = s[mt][0][2];
#pragma unroll
            for (int nt = 0; nt < 8; nt++) {
                mx0 = fmaxf(mx0, fmaxf(s[mt][nt][0], s[mt][nt][1]));
                mx1 = fmaxf(mx1, fmaxf(s[mt][nt][2], s[mt][nt][3]));
            }
            mx0 = fmaxf(mx0, __shfl_xor_sync(0xffffffffu, mx0, 1));
            mx0 = fmaxf(mx0, __shfl_xor_sync(0xffffffffu, mx0, 2));
            mx1 = fmaxf(mx1, __shfl_xor_sync(0xffffffffu, mx1, 1));
            mx1 = fmaxf(mx1, __shfl_xor_sync(0xffffffffu, mx1, 2));
            float mn0 = fmaxf(mrow[mt][0], mx0), mn1 = fmaxf(mrow[mt][1], mx1);
            float al0 = __expf(mrow[mt][0] - mn0), al1 = __expf(mrow[mt][1] - mn1);
            mrow[mt][0] = mn0; mrow[mt][1] = mn1;
            float sum0 = 0.0f, sum1 = 0.0f;
#pragma unroll
            for (int nt = 0; nt < 8; nt++) {
                s[mt][nt][0] = __expf(s[mt][nt][0] - mn0);
                s[mt][nt][1] = __expf(s[mt][nt][1] - mn0);
                s[mt][nt][2] = __expf(s[mt][nt][2] - mn1);
                s[mt][nt][3] = __expf(s[mt][nt][3] - mn1);
                sum0 += s[mt][nt][0] + s[mt][nt][1];
                sum1 += s[mt][nt][2] + s[mt][nt][3];
            }
            sum0 += __shfl_xor_sync(0xffffffffu, sum0, 1);
            sum0 += __shfl_xor_sync(0xffffffffu, sum0, 2);
            sum1 += __shfl_xor_sync(0xffffffffu, sum1, 1);
            sum1 += __shfl_xor_sync(0xffffffffu, sum1, 2);
            lrow[mt][0] = lrow[mt][0] * al0 + sum0;
            lrow[mt][1] = lrow[mt][1] * al1 + sum1;
#pragma unroll
            for (int dn = 0; dn < 8; dn++) {
                o[mt][dn][0] *= al0; o[mt][dn][1] *= al0;
                o[mt][dn][2] *= al1; o[mt][dn][3] *= al1;
            }
            const int r = wq + mt * 16 + lg;
#pragma unroll
            for (int nt = 0; nt < 8; nt++) {
                float2 t0, t1;
                t0.x = rna(s[mt][nt][0]); t0.y = rna(s[mt][nt][1]);
                t1.x = rna(s[mt][nt][2]); t1.y = rna(s[mt][nt][3]);
                *(float2*)(Ps + r * AP + nt * 8 + 2 * lk) = t0;
                *(float2*)(Ps + (r + 8) * AP + nt * 8 + 2 * lk) = t1;
            }
        }
        __syncwarp();

        // ---- O += P @ V (P via ldmatrix, V scalar) ----
#pragma unroll
        for (int ks = 0; ks < 8; ks++) {
            const int k0 = ks * 8;
            uint32_t a0[4], a1[4];
            LDSM_X4(a0[0], a0[1], a0[2], a0[3], padr[0] + ks * 32);
            LDSM_X4(a1[0], a1[1], a1[2], a1[3], padr[1] + ks * 32);
#pragma unroll
            for (int dn = 0; dn < 8; dn++) {
                uint32_t bf[2];
                bf[0] = __float_as_uint(Vs[(k0 + lk) * AV + dn * 8 + lg]);
                bf[1] = __float_as_uint(Vs[(k0 + 4 + lk) * AV + dn * 8 + lg]);
                mma_tf32(o[0][dn], a0, bf);
                mma_tf32(o[1][dn], a1, bf);
            }
        }
    }

#pragma unroll
    for (int mt = 0; mt < 2; mt++) {
        float inv0 = 1.0f / lrow[mt][0], inv1 = 1.0f / lrow[mt][1];
        const size_t r0 = (size_t)(b * LL + q0 + wq + mt * 16 + lg) * EE + h * DD;
        const size_t r1 = r0 + 8 * EE;
#pragma unroll
        for (int dn = 0; dn < 8; dn++) {
            const int col = dn * 8 + 2 * lk;
            float2 v0, v1;
            v0.x = rna(o[mt][dn][0] * inv0); v0.y = rna(o[mt][dn][1] * inv0);
            v1.x = rna(o[mt][dn][2] * inv1); v1.y = rna(o[mt][dn][3] * inv1);
            *(float2*)(g_ctx + r0 + col) = v0;
            *(float2*)(g_ctx + r1 + col) = v1;
        }
    }
}

// ---------------------------------------------------------------------------
// Launch
// ---------------------------------------------------------------------------
extern "C" void kernel_launch(void* const* d_in, const int* in_sizes, int n_in,
                              void* d_out, int out_size) {
    const float* queries = (const float*)d_in[0];
    const float* keys    = (const float*)d_in[1];
    const float* values  = (const float*)d_in[2];
    const int*   mask    = (const int*)d_in[3];
    const float* Wq      = (const float*)d_in[4];
    const float* Wk      = (const float*)d_in[5];
    const float* Wv      = (const float*)d_in[6];
    const float* Wo      = (const float*)d_in[7];
    const float* bo      = (const float*)d_in[8];
    float* out = (float*)d_out;

    float *q, *k, *v, *ctx, *rq, *rk, *rv, *rw;
    cudaGetSymbolAddress((void**)&q,   g_q);
    cudaGetSymbolAddress((void**)&k,   g_k);
    cudaGetSymbolAddress((void**)&v,   g_v);
    cudaGetSymbolAddress((void**)&ctx, g_ctx);
    cudaGetSymbolAddress((void**)&rq,  g_rq);
    cudaGetSymbolAddress((void**)&rk,  g_rk);
    cudaGetSymbolAddress((void**)&rv,  g_rv);
    cudaGetSymbolAddress((void**)&rw,  g_rw);

    cudaFuncSetAttribute(gemm_qkv, cudaFuncAttributeMaxDynamicSharedMemorySize,
                         GEMM_SMEM);
    cudaFuncSetAttribute(gemm_out, cudaFuncAttributeMaxDynamicSharedMemorySize,
                         GEMM_SMEM);
    cudaFuncSetAttribute(attn_tc, cudaFuncAttributeMaxDynamicSharedMemorySize,
                         ATTN_SMEM);

    RoundArgs ra;
    ra.src[0] = queries; ra.dst[0] = rq; ra.n4[0] = ML * EE / 4;
    ra.src[1] = keys;    ra.dst[1] = rk; ra.n4[1] = ML * EE / 4;
    ra.src[2] = values;  ra.dst[2] = rv; ra.n4[2] = ML * EE / 4;
    ra.src[3] = Wq; ra.dst[3] = rw + 0 * EE * EE; ra.n4[3] = EE * EE / 4;
    ra.src[4] = Wk; ra.dst[4] = rw + 1 * EE * EE; ra.n4[4] = EE * EE / 4;
    ra.src[5] = Wv; ra.dst[5] = rw + 2 * EE * EE; ra.n4[5] = EE * EE / 4;
    ra.src[6] = Wo; ra.dst[6] = rw + 3 * EE * EE; ra.n4[6] = EE * EE / 4;
    round_all<<<dim3(160, 7), 256>>>(ra);

    mask_to_bits<<<ML, 256>>>(mask);

    QkvArgs qa;
    qa.A[0] = rq; qa.A[1] = rk; qa.A[2] = rv;
    qa.W = rw;
    qa.C[0] = q; qa.C[1] = k; qa.C[2] = v;
    gemm_qkv<<<dim3(ML / 128, EE / 128, 3), 256, GEMM_SMEM>>>(qa);

    dim3 ga(LL / 256, BB * HH);    // 8 x 64
    attn_tc<<<ga, 256, ATTN_SMEM>>>();

    gemm_out<<<dim3(ML / 128, EE / 128), 256, GEMM_SMEM>>>(
        ctx, rw + 3 * EE * EE, bo, out);
}

// round 16
// speedup vs baseline: 1.5271x; 1.5271x over previous
#include <cuda_runtime.h>
#include <cstdint>
#include <math.h>

// Problem constants
#define BB 4
#define LL 2048
#define EE 1024
#define HH 16
#define DD 64
#define ML (BB * LL)   // 8192 total rows

// Scratch (device globals: allocation-free per harness rules)
__device__ float g_q[ML * EE];
__device__ float g_k[ML * EE];
__device__ float g_v[ML * EE];
__device__ float g_ctx[ML * EE];
__device__ float g_rq[ML * EE];
__device__ float g_rk[ML * EE];
__device__ float g_rv[ML * EE];
__device__ float g_rw[4 * EE * EE];
__device__ uint32_t g_mb[ML * (LL / 32)];   // mask bitmap: 2 MB

// ---------------------------------------------------------------------------
// Helpers
// ---------------------------------------------------------------------------
__device__ __forceinline__ uint32_t smem_u32(const void* p) {
    uint32_t a;
    asm("{ .reg .u64 t; cvta.to.shared.u64 t, %1; cvt.u32.u64 %0, t; }"
        : "=r"(a) : "l"(p));
    return a;
}

#define CP_ASYNC16(smem_addr, gptr) \
    asm volatile("cp.async.cg.shared.global [%0], [%1], 16;" \
                 :: "r"(smem_addr), "l"(gptr) : "memory")

__device__ __forceinline__ float rna(float f) {
    uint32_t r;
    asm("cvt.rna.tf32.f32 %0, %1;" : "=r"(r) : "f"(f));
    return __uint_as_float(r);
}

__device__ __forceinline__ void mma_tf32(float* c, const uint32_t* a,
                                         const uint32_t* b) {
    asm volatile(
        "mma.sync.aligned.m16n8k8.row.col.f32.tf32.tf32.f32 "
        "{%0,%1,%2,%3}, {%4,%5,%6,%7}, {%8,%9}, {%0,%1,%2,%3};"
        : "+f"(c[0]), "+f"(c[1]), "+f"(c[2]), "+f"(c[3])
        : "r"(a[0]), "r"(a[1]), "r"(a[2]), "r"(a[3]), "r"(b[0]), "r"(b[1]));
}

// ldmatrix x4: 4 m8n8.b16 tiles; for tf32 each tile = 8 rows x 4 floats.
// Lane i of tile t receives row i/4, float i%4 — the exact tf32 frag map.
// (Correctness of this mapping was verified bit-exact in an earlier round.)
#define LDSM_X4(r0, r1, r2, r3, addr) \
    asm volatile("ldmatrix.sync.aligned.m8n8.x4.shared.b16 {%0,%1,%2,%3}, [%4];" \
                 : "=r"(r0), "=r"(r1), "=r"(r2), "=r"(r3) : "r"(addr))

// ---------------------------------------------------------------------------
// Batched pre-rounding: one launch rounds all 7 arrays (blockIdx.y selects).
// ---------------------------------------------------------------------------
struct RoundArgs {
    const float* src[7];
    float* dst[7];
    int n4[7];
};

__global__ void round_all(RoundArgs ra) {
    const int a = blockIdx.y;
    const float4* s = (const float4*)ra.src[a];
    float4* d = (float4*)ra.dst[a];
    const int n4 = ra.n4[a];
    int i = blockIdx.x * blockDim.x + threadIdx.x;
    const int stride = gridDim.x * blockDim.x;
    for (; i < n4; i += stride) {
        float4 v = s[i];
        v.x = rna(v.x); v.y = rna(v.y); v.z = rna(v.z); v.w = rna(v.w);
        d[i] = v;
    }
}

// ---------------------------------------------------------------------------
// Mask -> bitmap: bit set = keep (mask != 0). 67 MB -> 2 MB, read once.
// ---------------------------------------------------------------------------
__global__ void mask_to_bits(const int* __restrict__ mask) {
    const int row = blockIdx.x;                    // 0 .. ML-1  (= b*LL + q)
    const int* mrow = mask + (size_t)row * LL;
    const int lane = threadIdx.x & 31;
    const int warp = threadIdx.x >> 5;
#pragma unroll
    for (int w = warp; w < LL / 32; w += 8) {
        const int v = mrow[w * 32 + lane];
        const uint32_t bits = __ballot_sync(0xffffffffu, v != 0);
        if (lane == 0) g_mb[row * (LL / 32) + w] = bits;
    }
}

// ---------------------------------------------------------------------------
// mma.sync tf32 GEMM v4: 3-stage pipeline, 1 barrier/k-tile, LDSM fragment
// loads (24 scalar LDS -> 6 LDSM.x4 per ks-step). regs had headroom (122).
// ---------------------------------------------------------------------------
#define GBK 32
#define NKT32 (EE / GBK)
#define SSTR 36
#define TILE_F (128 * SSTR)
#define STAGE_F (2 * TILE_F)
#define GSTAGES 3
#define GEMM_SMEM (GSTAGES * STAGE_F * 4)   // 110592 B

template <int ROUND_OUT>
__device__ __forceinline__ void gemm_body(const float* __restrict__ A,
                                          const float* __restrict__ W,
                                          const float* __restrict__ bias,
                                          float* __restrict__ C,
                                          float* sm) {
    const int tid = threadIdx.x;
    const int lane = tid & 31;
    const int warp = tid >> 5;
    const int wm = (warp >> 2) * 64;
    const int wn = (warp & 3) * 32;
    const int bm = blockIdx.x * 128;
    const int bn = blockIdx.y * 128;
    const uint32_t sb = smem_u32(sm);

    const int lrow = tid >> 3;
    const int lc4 = (tid & 7) * 4;
    const int lg = lane >> 2;
    const int lk = lane & 3;

    // LDSM lane geometry
    const int row8 = lane & 7;
    const int half = (lane >> 3) & 1;      // tile index bit 0
    const int quarter = (lane >> 4) & 1;   // tile index bit 1

    // A frag tiles (per mt): rows wm+mt*16+row8+half*8, col quarter*4
    uint32_t aoff[4];
#pragma unroll
    for (int mt = 0; mt < 4; mt++)
        aoff[mt] = (uint32_t)(((wm + mt * 16 + row8 + half * 8) * SSTR
                               + quarter * 4) * 4);
    // B frag tiles (per nt-pair p): rows wn+p*16+quarter*8+row8, col half*4
    uint32_t boff[2];
#pragma unroll
    for (int p = 0; p < 2; p++)
        boff[p] = (uint32_t)(((wn + p * 16 + quarter * 8 + row8) * SSTR
                              + half * 4) * 4 + TILE_F * 4);

    float c[4][4][4];
#pragma unroll
    for (int mt = 0; mt < 4; mt++)
#pragma unroll
        for (int nt = 0; nt < 4; nt++)
#pragma unroll
            for (int i = 0; i < 4; i++) c[mt][nt][i] = 0.0f;

    const float* gA0 = A + (size_t)(bm + lrow) * EE + lc4;
    const float* gW0 = W + (size_t)(bn + lrow) * EE + lc4;
    const uint32_t sOff = (lrow * SSTR + lc4) * 4;

#define LOAD_STAGE(kt, s) do {                                                 \
        const float* _ga = gA0 + (size_t)(kt) * GBK;                           \
        const float* _gw = gW0 + (size_t)(kt) * GBK;                           \
        uint32_t _sa = sb + (uint32_t)((s) * STAGE_F * 4) + sOff;              \
        uint32_t _sw = _sa + TILE_F * 4;                                       \
        _Pragma("unroll")                                                      \
        for (int _u = 0; _u < 4; _u++) {                                       \
            CP_ASYNC16(_sa + _u * 32 * SSTR * 4, _ga + (size_t)_u * 32 * EE);  \
            CP_ASYNC16(_sw + _u * 32 * SSTR * 4, _gw + (size_t)_u * 32 * EE);  \
        }                                                                      \
        asm volatile("cp.async.commit_group;" ::: "memory");                   \
    } while (0)

    LOAD_STAGE(0, 0);
    LOAD_STAGE(1, 1);

    for (int kt = 0; kt < NKT32; kt++) {
        if (kt + 1 < NKT32) {
            asm volatile("cp.async.wait_group 1;" ::: "memory");
        } else {
            asm volatile("cp.async.wait_group 0;" ::: "memory");
        }
        __syncthreads();

        if (kt + 2 < NKT32) LOAD_STAGE(kt + 2, (kt + 2) % GSTAGES);

        const uint32_t sst = sb + (uint32_t)((kt % GSTAGES) * STAGE_F * 4);

#pragma unroll
        for (int ks = 0; ks < 4; ks++) {
            const uint32_t kadd = (uint32_t)(ks * 32);   // +8 floats along K
            uint32_t bfr[4][2];
            LDSM_X4(bfr[0][0], bfr[0][1], bfr[1][0], bfr[1][1],
                    sst + boff[0] + kadd);
            LDSM_X4(bfr[2][0], bfr[2][1], bfr[3][0], bfr[3][1],
                    sst + boff[1] + kadd);
            uint32_t afr[4][4];
#pragma unroll
            for (int mt = 0; mt < 4; mt++)
                LDSM_X4(afr[mt][0], afr[mt][1], afr[mt][2], afr[mt][3],
                        sst + aoff[mt] + kadd);
#pragma unroll
            for (int mt = 0; mt < 4; mt++)
#pragma unroll
                for (int nt = 0; nt < 4; nt++)
                    mma_tf32(c[mt][nt], afr[mt], bfr[nt]);
        }
    }

#pragma unroll
    for (int mt = 0; mt < 4; mt++) {
        const int r0 = bm + wm + mt * 16 + lg;
#pragma unroll
        for (int nt = 0; nt < 4; nt++) {
            const int col = bn + wn + nt * 8 + lk * 2;
            float bx = 0.0f, by = 0.0f;
            if (bias) { bx = bias[col]; by = bias[col + 1]; }
            float2 v0, v1;
            v0.x = c[mt][nt][0] + bx;
            v0.y = c[mt][nt][1] + by;
            v1.x = c[mt][nt][2] + bx;
            v1.y = c[mt][nt][3] + by;
            if (ROUND_OUT) {
                v0.x = rna(v0.x); v0.y = rna(v0.y);
                v1.x = rna(v1.x); v1.y = rna(v1.y);
            }
            *(float2*)(C + (size_t)r0 * EE + col) = v0;
            *(float2*)(C + (size_t)(r0 + 8) * EE + col) = v1;
        }
    }
#undef LOAD_STAGE
}

struct QkvArgs {
    const float* A[3];
    const float* W;
    float* C[3];
};

__global__ __launch_bounds__(256, 2) void gemm_qkv(QkvArgs qa) {
    extern __shared__ float sm[];
    const int z = blockIdx.z;
    gemm_body<1>(qa.A[z], qa.W + (size_t)z * EE * EE, nullptr, qa.C[z], sm);
}

__global__ __launch_bounds__(256, 2) void gemm_out(const float* __restrict__ A,
                                                   const float* __restrict__ W,
                                                   const float* __restrict__ bias,
                                                   float* __restrict__ C) {
    extern __shared__ float sm[];
    gemm_body<0>(A, W, bias, C, sm);
}

// ---------------------------------------------------------------------------
// Tensor-core flash attention v3b: exact R12 WIN kernel + all-ones mask
// fast path (zero extra registers; loads stay at the point of use).
// ---------------------------------------------------------------------------
#define AQ 68
#define AK 68
#define AV 72
#define AP 68
#define QF (256 * AQ)
#define STGF (64 * AK + 64 * AV)
#define PF (256 * AP)
#define ATTN_SMEM ((QF + 2 * STGF + PF) * 4)   // 210944 B

__global__ __launch_bounds__(256, 1) void attn_tc() {
    extern __shared__ float sm[];
    float* Qs = sm;
    float* St = Qs + QF;
    float* Ps = St + 2 * STGF;

    const int tid = threadIdx.x;
    const int lane = tid & 31;
    const int warp = tid >> 5;
    const int lg = lane >> 2;
    const int lk = lane & 3;
    const int wq = warp * 32;

    const int bh = blockIdx.y;
    const int b = bh >> 4;
    const int h = bh & 15;
    const int q0 = blockIdx.x * 256;

    const float scale = 0.03125f;
    const float mask_addend = -3.125e18f;

    const uint32_t sb = smem_u32(sm);
    const int ldr = tid >> 4;
    const int ldc = (tid & 15) << 2;

#define PREFETCH_KV(kt, bufsel) do {                                            \
        const uint32_t so = sb + (uint32_t)(QF + (bufsel) * STGF) * 4;          \
        _Pragma("unroll")                                                       \
        for (int _u = 0; _u < 4; _u++) {                                        \
            const int _row = ldr + 16 * _u;                                     \
            const size_t _g = (size_t)(b * LL + (kt) * 64 + _row) * EE          \
                              + h * DD + ldc;                                   \
            CP_ASYNC16(so + (uint32_t)(_row * AK + ldc) * 4, g_k + _g);         \
            CP_ASYNC16(so + (uint32_t)(64 * AK + _row * AV + ldc) * 4,          \
                       g_v + _g);                                               \
        }                                                                       \
        asm volatile("cp.async.commit_group;" ::: "memory");                    \
    } while (0)

    PREFETCH_KV(0, 0);

#pragma unroll
    for (int u = 0; u < 16; u++) {
        int idx = tid + 256 * u;
        int row = idx >> 4;
        int c = (idx & 15) << 2;
        float4 q = *(const float4*)(g_q + (size_t)(b * LL + q0 + row) * EE + h * DD + c);
        q.x *= scale; q.y *= scale; q.z *= scale; q.w *= scale;
        *(float4*)(Qs + row * AQ + c) = q;
    }

    float o[2][8][4];
#pragma unroll
    for (int mt = 0; mt < 2; mt++)
#pragma unroll
        for (int dn = 0; dn < 8; dn++)
#pragma unroll
            for (int j = 0; j < 4; j++) o[mt][dn][j] = 0.0f;
    float mrow[2][2], lrow[2][2];
#pragma unroll
    for (int mt = 0; mt < 2; mt++) {
        mrow[mt][0] = -1e30f; mrow[mt][1] = -1e30f;
        lrow[mt][0] = 0.0f;   lrow[mt][1] = 0.0f;
    }

    for (int kt = 0; kt < LL / 64; kt++) {
        const int k0g = kt * 64;
        const int buf = kt & 1;

        asm volatile("cp.async.wait_group 0;" ::: "memory");
        __syncthreads();

        if (kt + 1 < LL / 64) PREFETCH_KV(kt + 1, buf ^ 1);

        const float* Ks = St + buf * STGF;
        const float* Vs = Ks + 64 * AK;

        float s[2][8][4];
#pragma unroll
        for (int mt = 0; mt < 2; mt++)
#pragma unroll
            for (int nt = 0; nt < 8; nt++)
#pragma unroll
                for (int j = 0; j < 4; j++) s[mt][nt][j] = 0.0f;

#pragma unroll
        for (int ks = 0; ks < 8; ks++) {
            const int k0 = ks * 8;
            uint32_t a[2][4];
#pragma unroll
            for (int mt = 0; mt < 2; mt++) {
                const int r = wq + mt * 16 + lg;
                a[mt][0] = __float_as_uint(Qs[r * AQ + k0 + lk]);
                a[mt][1] = __float_as_uint(Qs[(r + 8) * AQ + k0 + lk]);
                a[mt][2] = __float_as_uint(Qs[r * AQ + k0 + 4 + lk]);
                a[mt][3] = __float_as_uint(Qs[(r + 8) * AQ + k0 + 4 + lk]);
            }
#pragma unroll
            for (int nt = 0; nt < 8; nt++) {
                uint32_t bf[2];
                bf[0] = __float_as_uint(Ks[(nt * 8 + lg) * AK + k0 + lk]);
                bf[1] = __float_as_uint(Ks[(nt * 8 + lg) * AK + k0 + 4 + lk]);
                mma_tf32(s[0][nt], a[0], bf);
                mma_tf32(s[1][nt], a[1], bf);
            }
        }

        // ---- mask from bitmap (skip all work when segment is all-ones) ----
#pragma unroll
        for (int mt = 0; mt < 2; mt++) {
            const int qrow = q0 + wq + mt * 16 + lg;
            const int base = (b * LL + qrow) * (LL / 32) + (k0g >> 5);
            uint2 w0 = *(const uint2*)(g_mb + base);
            uint2 w1 = *(const uint2*)(g_mb + base + 8 * (LL / 32));
            if ((w0.x & w0.y & w1.x & w1.y) != 0xffffffffu) {
                const uint64_t m0 = (uint64_t)w0.x | ((uint64_t)w0.y << 32);
                const uint64_t m1 = (uint64_t)w1.x | ((uint64_t)w1.y << 32);
#pragma unroll
                for (int nt = 0; nt < 8; nt++) {
                    const int c = nt * 8 + 2 * lk;
                    if (!((m0 >> c) & 1))       s[mt][nt][0] = mask_addend;
                    if (!((m0 >> (c + 1)) & 1)) s[mt][nt][1] = mask_addend;
                    if (!((m1 >> c) & 1))       s[mt][nt][2] = mask_addend;
                    if (!((m1 >> (c + 1)) & 1)) s[mt][nt][3] = mask_addend;
                }
            }
        }

#pragma unroll
        for (int mt = 0; mt < 2; mt++) {
            float mx0 = s[mt][0][0], mx1 = s[mt][0][2];
#pragma unroll
            for (int nt = 0; nt < 8; nt++) {
                mx0 = fmaxf(mx0, fmaxf(s[mt][nt][0], s[mt][nt][1]));
                mx1 = fmaxf(mx1, fmaxf(s[mt][nt][2], s[mt][nt][3]));
            }
            mx0 = fmaxf(mx0, __shfl_xor_sync(0xffffffffu, mx0, 1));
            mx0 = fmaxf(mx0, __shfl_xor_sync(0xffffffffu, mx0, 2));
            mx1 = fmaxf(mx1, __shfl_xor_sync(0xffffffffu, mx1, 1));
            mx1 = fmaxf(mx1, __shfl_xor_sync(0xffffffffu, mx1, 2));
            float mn0 = fmaxf(mrow[mt][0], mx0), mn1 = fmaxf(mrow[mt][1], mx1);
            float al0 = __expf(mrow[mt][0] - mn0), al1 = __expf(mrow[mt][1] - mn1);
            mrow[mt][0] = mn0; mrow[mt][1] = mn1;
            float sum0 = 0.0f, sum1 = 0.0f;
#pragma unroll
            for (int nt = 0; nt < 8; nt++) {
                s[mt][nt][0] = __expf(s[mt][nt][0] - mn0);
                s[mt][nt][1] = __expf(s[mt][nt][1] - mn0);
                s[mt][nt][2] = __expf(s[mt][nt][2] - mn1);
                s[mt][nt][3] = __expf(s[mt][nt][3] - mn1);
                sum0 += s[mt][nt][0] + s[mt][nt][1];
                sum1 += s[mt][nt][2] + s[mt][nt][3];
            }
            sum0 += __shfl_xor_sync(0xffffffffu, sum0, 1);
            sum0 += __shfl_xor_sync(0xffffffffu, sum0, 2);
            sum1 += __shfl_xor_sync(0xffffffffu, sum1, 1);
            sum1 += __shfl_xor_sync(0xffffffffu, sum1, 2);
            lrow[mt][0] = lrow[mt][0] * al0 + sum0;
            lrow[mt][1] = lrow[mt][1] * al1 + sum1;
#pragma unroll
            for (int dn = 0; dn < 8; dn++) {
                o[mt][dn][0] *= al0; o[mt][dn][1] *= al0;
                o[mt][dn][2] *= al1; o[mt][dn][3] *= al1;
            }
            const int r = wq + mt * 16 + lg;
#pragma unroll
            for (int nt = 0; nt < 8; nt++) {
                float2 t0, t1;
                t0.x = rna(s[mt][nt][0]); t0.y = rna(s[mt][nt][1]);
                t1.x = rna(s[mt][nt][2]); t1.y = rna(s[mt][nt][3]);
                *(float2*)(Ps + r * AP + nt * 8 + 2 * lk) = t0;
                *(float2*)(Ps + (r + 8) * AP + nt * 8 + 2 * lk) = t1;
            }
        }
        __syncwarp();

#pragma unroll
        for (int ks = 0; ks < 8; ks++) {
            const int k0 = ks * 8;
            uint32_t a[2][4];
#pragma unroll
            for (int mt = 0; mt < 2; mt++) {
                const int r = wq + mt * 16 + lg;
                a[mt][0] = __float_as_uint(Ps[r * AP + k0 + lk]);
                a[mt][1] = __float_as_uint(Ps[(r + 8) * AP + k0 + lk]);
                a[mt][2] = __float_as_uint(Ps[r * AP + k0 + 4 + lk]);
                a[mt][3] = __float_as_uint(Ps[(r + 8) * AP + k0 + 4 + lk]);
            }
#pragma unroll
            for (int dn = 0; dn < 8; dn++) {
                uint32_t bf[2];
                bf[0] = __float_as_uint(Vs[(k0 + lk) * AV + dn * 8 + lg]);
                bf[1] = __float_as_uint(Vs[(k0 + 4 + lk) * AV + dn * 8 + lg]);
                mma_tf32(o[0][dn], a[0], bf);
                mma_tf32(o[1][dn], a[1], bf);
            }
        }
    }

#pragma unroll
    for (int mt = 0; mt < 2; mt++) {
        float inv0 = 1.0f / lrow[mt][0], inv1 = 1.0f / lrow[mt][1];
        const size_t r0 = (size_t)(b * LL + q0 + wq + mt * 16 + lg) * EE + h * DD;
        const size_t r1 = r0 + 8 * EE;
#pragma unroll
        for (int dn = 0; dn < 8; dn++) {
            const int col = dn * 8 + 2 * lk;
            float2 v0, v1;
            v0.x = rna(o[mt][dn][0] * inv0); v0.y = rna(o[mt][dn][1] * inv0);
            v1.x = rna(o[mt][dn][2] * inv1); v1.y = rna(o[mt][dn][3] * inv1);
            *(float2*)(g_ctx + r0 + col) = v0;
            *(float2*)(g_ctx + r1 + col) = v1;
        }
    }
}

// ---------------------------------------------------------------------------
// Launch
// ---------------------------------------------------------------------------
extern "C" void kernel_launch(void* const* d_in, const int* in_sizes, int n_in,
                              void* d_out, int out_size) {
    const float* queries = (const float*)d_in[0];
    const float* keys    = (const float*)d_in[1];
    const float* values  = (const float*)d_in[2];
    const int*   mask    = (const int*)d_in[3];
    const float* Wq      = (const float*)d_in[4];
    const float* Wk      = (const float*)d_in[5];
    const float* Wv      = (const float*)d_in[6];
    const float* Wo      = (const float*)d_in[7];
    const float* bo      = (const float*)d_in[8];
    float* out = (float*)d_out;

    float *q, *k, *v, *ctx, *rq, *rk, *rv, *rw;
    cudaGetSymbolAddress((void**)&q,   g_q);
    cudaGetSymbolAddress((void**)&k,   g_k);
    cudaGetSymbolAddress((void**)&v,   g_v);
    cudaGetSymbolAddress((void**)&ctx, g_ctx);
    cudaGetSymbolAddress((void**)&rq,  g_rq);
    cudaGetSymbolAddress((void**)&rk,  g_rk);
    cudaGetSymbolAddress((void**)&rv,  g_rv);
    cudaGetSymbolAddress((void**)&rw,  g_rw);

    cudaFuncSetAttribute(gemm_qkv, cudaFuncAttributeMaxDynamicSharedMemorySize,
                         GEMM_SMEM);
    cudaFuncSetAttribute(gemm_out, cudaFuncAttributeMaxDynamicSharedMemorySize,
                         GEMM_SMEM);
    cudaFuncSetAttribute(attn_tc, cudaFuncAttributeMaxDynamicSharedMemorySize,
                         ATTN_SMEM);

    RoundArgs ra;
    ra.src[0] = queries; ra.dst[0] = rq; ra.n4[0] = ML * EE / 4;
    ra.src[1] = keys;    ra.dst[1] = rk; ra.n4[1] = ML * EE / 4;
    ra.src[2] = values;  ra.dst[2] = rv; ra.n4[2] = ML * EE / 4;
    ra.src[3] = Wq; ra.dst[3] = rw + 0 * EE * EE; ra.n4[3] = EE * EE / 4;
    ra.src[4] = Wk; ra.dst[4] = rw + 1 * EE * EE; ra.n4[4] = EE * EE / 4;
    ra.src[5] = Wv; ra.dst[5] = rw + 2 * EE * EE; ra.n4[5] = EE * EE / 4;
    ra.src[6] = Wo; ra.dst[6] = rw + 3 * EE * EE; ra.n4[6] = EE * EE / 4;
    round_all<<<dim3(160, 7), 256>>>(ra);

    mask_to_bits<<<ML, 256>>>(mask);

    QkvArgs qa;
    qa.A[0] = rq; qa.A[1] = rk; qa.A[2] = rv;
    qa.W = rw;
    qa.C[0] = q; qa.C[1] = k; qa.C[2] = v;
    gemm_qkv<<<dim3(ML / 128, EE / 128, 3), 256, GEMM_SMEM>>>(qa);

    dim3 ga(LL / 256, BB * HH);    // 8 x 64
    attn_tc<<<ga, 256, ATTN_SMEM>>>();

    gemm_out<<<dim3(ML / 128, EE / 128), 256, GEMM_SMEM>>>(
        ctx, rw + 3 * EE * EE, bo, out);
}